// round 13
// baseline (speedup 1.0000x reference)
#include <cuda_runtime.h>

// Problem constants
#define B_      256
#define L_      2048
#define V_      8
#define NS_     5        // shapelets
#define BAG_    409
#define BAGP_   416      // padded (zero-filled) shapelet length in smem
#define SHIFT_  204
#define NB_     9        // windows
#define FEAT_   80       // 2*NS*V
#define NCLASS_ 10
#define BN_EPS_ 1e-5f
#define RSTRIDE_ 57      // padded reduction row stride (conflict-free)

// Scratch
__device__ float g_featT[FEAT_ * B_];   // transposed features [f][b]
__device__ int   g_ctr = 0;             // last-block ticket (self-resetting)

#define K1_WARPS_   8
#define K1_THREADS_ 256
#define RED_FLOATS_ (K1_WARPS_ * 32 * RSTRIDE_)
#define K1_DSMEM_   (RED_FLOATS_ * sizeof(float))

// ---------------------------------------------------------------------------
// Fused kernel: block = (8 batches, 1 v), one warp per (b,v). Grid 256.
// Main body identical to the best-measured (12.96us) variant:
//   3 float4 chunks + scalar tail; nb split into 5/4 register groups;
//   smem transpose reduction; epilogue lanes 0..4 per warp.
// Tail: the LAST block (atomic ticket) computes BN batch stats + FC for the
// whole batch — replaces two kernel launches and their gaps.
// ---------------------------------------------------------------------------
__global__ __launch_bounds__(K1_THREADS_, 2)
void shapelet_fused_kernel(const float* __restrict__ x,
                           const float* __restrict__ shp,
                           const float* __restrict__ gamma,
                           const float* __restrict__ beta,
                           const float* __restrict__ fcw,
                           const float* __restrict__ fcb,
                           float* __restrict__ featT,
                           float* __restrict__ out)
{
    extern __shared__ float red[];          // [8][32][RSTRIDE_]
    __shared__ float s_shp[NS_][BAGP_];
    __shared__ float s_ss2[NS_];
    // tail staging (only used by the last block)
    __shared__ float s_scale[FEAT_];
    __shared__ float s_shift[FEAT_];
    __shared__ float s_w[NCLASS_ * FEAT_];
    __shared__ float s_fb[NCLASS_];
    __shared__ int   s_islast;

    const int tid  = threadIdx.x;
    const int warp = tid >> 5;
    const int lane = tid & 31;
    const int v  = blockIdx.x & 7;
    const int b  = (blockIdx.x >> 3) * 8 + warp;

    // Stage shapelets (zero-pad 409..415)
    for (int i = tid; i < NS_ * BAGP_; i += K1_THREADS_) {
        const int s = i / BAGP_;
        const int t = i - s * BAGP_;
        s_shp[s][t] = (t < BAG_) ? shp[s * (V_ * BAG_) + v * BAG_ + t] : 0.f;
    }
    __syncthreads();

    // ss2[s]: warps 0..4, one shapelet each
    if (warp < NS_) {
        float q = 0.f;
        for (int t = lane; t < BAG_; t += 32) {
            const float sv = s_shp[warp][t];
            q = fmaf(sv, sv, q);
        }
#pragma unroll
        for (int o = 16; o > 0; o >>= 1) q += __shfl_xor_sync(0xffffffffu, q, o);
        if (lane == 0) s_ss2[warp] = q;
    }

    // ---- main accumulation (nb split into groups of 5/4) ----
    const float* __restrict__ xr = x + (size_t)b * (V_ * L_) + (size_t)v * L_;
    const float* __restrict__ xr4 = xr + 4 * lane;

    float c[NS_][NB_];
    float sx2[NB_];
#pragma unroll
    for (int s = 0; s < NS_; s++)
#pragma unroll
        for (int nb = 0; nb < NB_; nb++) c[s][nb] = 0.f;
#pragma unroll
    for (int nb = 0; nb < NB_; nb++) sx2[nb] = 0.f;

#pragma unroll
    for (int k = 0; k < 3; k++) {
        const int t0 = 128 * k + 4 * lane;

        {   // group 0: nb 0..4
            float4 xv[5];
#pragma unroll
            for (int j = 0; j < 5; j++)
                xv[j] = *(const float4*)(xr4 + j * SHIFT_ + 128 * k);
#pragma unroll
            for (int j = 0; j < 5; j++) {
                sx2[j] = fmaf(xv[j].x, xv[j].x, sx2[j]);
                sx2[j] = fmaf(xv[j].y, xv[j].y, sx2[j]);
                sx2[j] = fmaf(xv[j].z, xv[j].z, sx2[j]);
                sx2[j] = fmaf(xv[j].w, xv[j].w, sx2[j]);
            }
#pragma unroll
            for (int s = 0; s < NS_; s++) {
                const float4 sw = *(const float4*)(&s_shp[s][t0]);
#pragma unroll
                for (int j = 0; j < 5; j++) {
                    c[s][j] = fmaf(xv[j].x, sw.x, c[s][j]);
                    c[s][j] = fmaf(xv[j].y, sw.y, c[s][j]);
                    c[s][j] = fmaf(xv[j].z, sw.z, c[s][j]);
                    c[s][j] = fmaf(xv[j].w, sw.w, c[s][j]);
                }
            }
        }
        {   // group 1: nb 5..8
            float4 xv[4];
#pragma unroll
            for (int j = 0; j < 4; j++)
                xv[j] = *(const float4*)(xr4 + (5 + j) * SHIFT_ + 128 * k);
#pragma unroll
            for (int j = 0; j < 4; j++) {
                sx2[5 + j] = fmaf(xv[j].x, xv[j].x, sx2[5 + j]);
                sx2[5 + j] = fmaf(xv[j].y, xv[j].y, sx2[5 + j]);
                sx2[5 + j] = fmaf(xv[j].z, xv[j].z, sx2[5 + j]);
                sx2[5 + j] = fmaf(xv[j].w, xv[j].w, sx2[5 + j]);
            }
#pragma unroll
            for (int s = 0; s < NS_; s++) {
                const float4 sw = *(const float4*)(&s_shp[s][t0]);
#pragma unroll
                for (int j = 0; j < 4; j++) {
                    c[s][5 + j] = fmaf(xv[j].x, sw.x, c[s][5 + j]);
                    c[s][5 + j] = fmaf(xv[j].y, sw.y, c[s][5 + j]);
                    c[s][5 + j] = fmaf(xv[j].z, sw.z, c[s][5 + j]);
                    c[s][5 + j] = fmaf(xv[j].w, sw.w, c[s][5 + j]);
                }
            }
        }
    }

    // scalar tail: t = 384 + lane, valid for lane < 25
    {
        const int t = 384 + lane;
        const bool ok = (lane < 25);
        float xs[NB_];
#pragma unroll
        for (int nb = 0; nb < NB_; nb++)
            xs[nb] = ok ? xr[nb * SHIFT_ + t] : 0.f;
#pragma unroll
        for (int nb = 0; nb < NB_; nb++)
            sx2[nb] = fmaf(xs[nb], xs[nb], sx2[nb]);
#pragma unroll
        for (int s = 0; s < NS_; s++) {
            const float sv = s_shp[s][t];
#pragma unroll
            for (int nb = 0; nb < NB_; nb++)
                c[s][nb] = fmaf(xs[nb], sv, c[s][nb]);
        }
    }

    // ---- smem transpose reduction ----
    float* base = red + warp * (32 * RSTRIDE_);
    {
        float* my = base + lane * RSTRIDE_;
#pragma unroll
        for (int nb = 0; nb < NB_; nb++) my[nb] = sx2[nb];
#pragma unroll
        for (int s = 0; s < NS_; s++)
#pragma unroll
            for (int nb = 0; nb < NB_; nb++) my[NB_ + s * NB_ + nb] = c[s][nb];
    }
    __syncwarp();

    float tot0, tot1;
    if (lane < 27) {
        float a0 = 0.f, a1 = 0.f, b0 = 0.f, b1 = 0.f;
#pragma unroll
        for (int l = 0; l < 32; l += 2) {
            a0 += base[l * RSTRIDE_ + lane];
            a1 += base[(l + 1) * RSTRIDE_ + lane];
            b0 += base[l * RSTRIDE_ + lane + 27];
            b1 += base[(l + 1) * RSTRIDE_ + lane + 27];
        }
        tot0 = a0 + a1;
        tot1 = b0 + b1;
    }
    __syncwarp();
    if (lane < 27) {
        base[lane]      = tot0;
        base[lane + 27] = tot1;
    }
    __syncthreads();                         // totals + s_ss2 visible

    // ---- epilogue: lanes 0..4 handle shapelet s = lane; write TRANSPOSED ----
    if (lane < NS_) {
        const int s = lane;
        const float ss2v = s_ss2[s];
        float dmin = 3.402823466e+38f;
        float dsum = 0.f;
#pragma unroll
        for (int nb = 0; nb < NB_; nb++) {
            const float sx2t = base[nb];
            const float ct   = base[NB_ + s * NB_ + nb];
            const float d2 = sx2t + ss2v - 2.f * ct;
            const float d  = sqrtf(fmaxf(d2, 0.f));
            dmin = fminf(dmin, d);
            dsum += d;
        }
        featT[(s * V_ + v) * B_ + b]              = dmin;
        featT[(NS_ * V_ + s * V_ + v) * B_ + b]   = dsum * (1.f / 9.f);
        __threadfence();                     // publish before ticket
    }

    // ---- last-block gate ----
    __syncthreads();
    if (tid == 0) {
        const int t = atomicAdd(&g_ctr, 1);
        s_islast = (t == (int)gridDim.x - 1);
        if (s_islast) g_ctr = 0;             // self-reset for next launch/replay
    }
    __syncthreads();
    if (!s_islast) return;
    __threadfence();                          // acquire side

    // ============== TAIL (one block): BN stats + FC ==============

    // stage FC weights + bias
    for (int i = tid; i < NCLASS_ * FEAT_; i += K1_THREADS_) s_w[i] = fcw[i];
    if (tid < NCLASS_) s_fb[tid] = fcb[tid];

    // stats: warp w handles features w*10 .. w*10+9; lane holds 8 col values
    {
#pragma unroll
        for (int i = 0; i < 10; i++) {
            const int f = warp * 10 + i;
            const float4* col = (const float4*)(featT + f * B_);
            const float4 A  = col[lane];
            const float4 Bv = col[lane + 32];
            float sum = (A.x + A.y) + (A.z + A.w) + (Bv.x + Bv.y) + (Bv.z + Bv.w);
#pragma unroll
            for (int o = 16; o > 0; o >>= 1) sum += __shfl_xor_sync(0xffffffffu, sum, o);
            const float mu = sum * (1.f / 256.f);
            float q = (A.x - mu) * (A.x - mu) + (A.y - mu) * (A.y - mu)
                    + (A.z - mu) * (A.z - mu) + (A.w - mu) * (A.w - mu)
                    + (Bv.x - mu) * (Bv.x - mu) + (Bv.y - mu) * (Bv.y - mu)
                    + (Bv.z - mu) * (Bv.z - mu) + (Bv.w - mu) * (Bv.w - mu);
#pragma unroll
            for (int o = 16; o > 0; o >>= 1) q += __shfl_xor_sync(0xffffffffu, q, o);
            if (lane == 0) {
                const float var  = q * (1.f / 256.f);
                const float rstd = rsqrtf(var + BN_EPS_);
                const float sc   = gamma[f] * rstd;
                s_scale[f] = sc;
                s_shift[f] = beta[f] - mu * sc;
            }
        }
    }
    __syncthreads();

    // FC: thread = batch row; coalesced featT loads, smem broadcasts
    {
        float acc[NCLASS_];
#pragma unroll
        for (int cc = 0; cc < NCLASS_; cc++) acc[cc] = s_fb[cc];
#pragma unroll 4
        for (int f = 0; f < FEAT_; f++) {
            const float val = fmaf(featT[f * B_ + tid], s_scale[f], s_shift[f]);
#pragma unroll
            for (int cc = 0; cc < NCLASS_; cc++)
                acc[cc] = fmaf(val, s_w[cc * FEAT_ + f], acc[cc]);
        }
#pragma unroll
        for (int cc = 0; cc < NCLASS_; cc++)
            out[tid * NCLASS_ + cc] = acc[cc];
    }
}

// ---------------------------------------------------------------------------
extern "C" void kernel_launch(void* const* d_in, const int* in_sizes, int n_in,
                              void* d_out, int out_size)
{
    const float* x     = (const float*)d_in[0];  // [256, 2048, 8]
    const float* shp   = (const float*)d_in[1];  // [1, 5, 8, 409, 1]
    const float* gamma = (const float*)d_in[2];  // [80]
    const float* beta  = (const float*)d_in[3];  // [80]
    const float* fcw   = (const float*)d_in[4];  // [10, 80]
    const float* fcb   = (const float*)d_in[5];  // [10]
    float* out = (float*)d_out;                  // [256, 10]

    float* featT = nullptr;
    cudaGetSymbolAddress((void**)&featT, g_featT);

    static bool attr_set = false;
    if (!attr_set) {
        cudaFuncSetAttribute(shapelet_fused_kernel,
                             cudaFuncAttributeMaxDynamicSharedMemorySize,
                             (int)K1_DSMEM_);
        attr_set = true;
    }

    shapelet_fused_kernel<<<256, K1_THREADS_, K1_DSMEM_>>>(
        x, shp, gamma, beta, fcw, fcb, featT, out);
}

// round 14
// speedup vs baseline: 1.2305x; 1.2305x over previous
#include <cuda_runtime.h>

// Problem constants
#define B_      256
#define L_      2048
#define V_      8
#define NS_     5        // shapelets
#define BAG_    409
#define BAGP_   416      // padded (zero-filled) shapelet length in smem
#define SHIFT_  204
#define NB_     9        // windows
#define FEAT_   80       // 2*NS*V
#define NCLASS_ 10
#define BN_EPS_ 1e-5f
#define RSTRIDE_ 57      // padded reduction row stride (conflict-free)

// Scratch
__device__ float g_feat[B_ * FEAT_];
__device__ float g_scale[FEAT_];
__device__ float g_shift[FEAT_];
__device__ int   g_done = 0;      // stats-done counter (self-resetting)
__device__ int   g_fc_done = 0;   // fc-block completion counter

#define RED_FLOATS_ (8 * 32 * RSTRIDE_)          // per-block reduction scratch
#define K1_DSMEM_   (RED_FLOATS_ * sizeof(float))

// ---------------------------------------------------------------------------
// Kernel 1 — UNCHANGED champion body (12.96us measured): block = (8 batches,
// 1 v), one warp per (b,v). 3 float4 chunks + scalar tail; nb split 5/4;
// smem transpose reduction; epilogue lanes 0..4.
// ---------------------------------------------------------------------------
__global__ __launch_bounds__(256, 2)
void shapelet_feat_kernel(const float* __restrict__ x,
                          const float* __restrict__ shp,
                          float* __restrict__ feat)
{
    extern __shared__ float red[];          // [8][32][RSTRIDE_]
    __shared__ float s_shp[NS_][BAGP_];
    __shared__ float s_ss2[NS_];

    const int tid  = threadIdx.x;
    const int warp = tid >> 5;
    const int lane = tid & 31;
    const int v  = blockIdx.x & 7;
    const int b  = (blockIdx.x >> 3) * 8 + warp;

    // Stage shapelets (zero-pad 409..415)
    for (int i = tid; i < NS_ * BAGP_; i += 256) {
        const int s = i / BAGP_;
        const int t = i - s * BAGP_;
        s_shp[s][t] = (t < BAG_) ? shp[s * (V_ * BAG_) + v * BAG_ + t] : 0.f;
    }
    __syncthreads();

    // ss2[s]: warps 0..4, one shapelet each
    if (warp < NS_) {
        float q = 0.f;
        for (int t = lane; t < BAG_; t += 32) {
            const float sv = s_shp[warp][t];
            q = fmaf(sv, sv, q);
        }
#pragma unroll
        for (int o = 16; o > 0; o >>= 1) q += __shfl_xor_sync(0xffffffffu, q, o);
        if (lane == 0) s_ss2[warp] = q;
    }

    // ---- main accumulation (nb split into groups of 5/4 to bound live regs) ----
    const float* __restrict__ xr = x + (size_t)b * (V_ * L_) + (size_t)v * L_;
    const float* __restrict__ xr4 = xr + 4 * lane;

    float c[NS_][NB_];
    float sx2[NB_];
#pragma unroll
    for (int s = 0; s < NS_; s++)
#pragma unroll
        for (int nb = 0; nb < NB_; nb++) c[s][nb] = 0.f;
#pragma unroll
    for (int nb = 0; nb < NB_; nb++) sx2[nb] = 0.f;

#pragma unroll
    for (int k = 0; k < 3; k++) {
        const int t0 = 128 * k + 4 * lane;

        {   // group 0: nb 0..4
            float4 xv[5];
#pragma unroll
            for (int j = 0; j < 5; j++)
                xv[j] = *(const float4*)(xr4 + j * SHIFT_ + 128 * k);
#pragma unroll
            for (int j = 0; j < 5; j++) {
                sx2[j] = fmaf(xv[j].x, xv[j].x, sx2[j]);
                sx2[j] = fmaf(xv[j].y, xv[j].y, sx2[j]);
                sx2[j] = fmaf(xv[j].z, xv[j].z, sx2[j]);
                sx2[j] = fmaf(xv[j].w, xv[j].w, sx2[j]);
            }
#pragma unroll
            for (int s = 0; s < NS_; s++) {
                const float4 sw = *(const float4*)(&s_shp[s][t0]);
#pragma unroll
                for (int j = 0; j < 5; j++) {
                    c[s][j] = fmaf(xv[j].x, sw.x, c[s][j]);
                    c[s][j] = fmaf(xv[j].y, sw.y, c[s][j]);
                    c[s][j] = fmaf(xv[j].z, sw.z, c[s][j]);
                    c[s][j] = fmaf(xv[j].w, sw.w, c[s][j]);
                }
            }
        }
        {   // group 1: nb 5..8
            float4 xv[4];
#pragma unroll
            for (int j = 0; j < 4; j++)
                xv[j] = *(const float4*)(xr4 + (5 + j) * SHIFT_ + 128 * k);
#pragma unroll
            for (int j = 0; j < 4; j++) {
                sx2[5 + j] = fmaf(xv[j].x, xv[j].x, sx2[5 + j]);
                sx2[5 + j] = fmaf(xv[j].y, xv[j].y, sx2[5 + j]);
                sx2[5 + j] = fmaf(xv[j].z, xv[j].z, sx2[5 + j]);
                sx2[5 + j] = fmaf(xv[j].w, xv[j].w, sx2[5 + j]);
            }
#pragma unroll
            for (int s = 0; s < NS_; s++) {
                const float4 sw = *(const float4*)(&s_shp[s][t0]);
#pragma unroll
                for (int j = 0; j < 4; j++) {
                    c[s][5 + j] = fmaf(xv[j].x, sw.x, c[s][5 + j]);
                    c[s][5 + j] = fmaf(xv[j].y, sw.y, c[s][5 + j]);
                    c[s][5 + j] = fmaf(xv[j].z, sw.z, c[s][5 + j]);
                    c[s][5 + j] = fmaf(xv[j].w, sw.w, c[s][5 + j]);
                }
            }
        }
    }

    // scalar tail: t = 384 + lane, valid for lane < 25
    {
        const int t = 384 + lane;
        const bool ok = (lane < 25);
        float xs[NB_];
#pragma unroll
        for (int nb = 0; nb < NB_; nb++)
            xs[nb] = ok ? xr[nb * SHIFT_ + t] : 0.f;
#pragma unroll
        for (int nb = 0; nb < NB_; nb++)
            sx2[nb] = fmaf(xs[nb], xs[nb], sx2[nb]);
#pragma unroll
        for (int s = 0; s < NS_; s++) {
            const float sv = s_shp[s][t];
#pragma unroll
            for (int nb = 0; nb < NB_; nb++)
                c[s][nb] = fmaf(xs[nb], sv, c[s][nb]);
        }
    }

    // ---- smem transpose reduction ----
    float* base = red + warp * (32 * RSTRIDE_);
    {
        float* my = base + lane * RSTRIDE_;
#pragma unroll
        for (int nb = 0; nb < NB_; nb++) my[nb] = sx2[nb];
#pragma unroll
        for (int s = 0; s < NS_; s++)
#pragma unroll
            for (int nb = 0; nb < NB_; nb++) my[NB_ + s * NB_ + nb] = c[s][nb];
    }
    __syncwarp();

    float tot0, tot1;
    if (lane < 27) {
        float a0 = 0.f, a1 = 0.f, b0 = 0.f, b1 = 0.f;
#pragma unroll
        for (int l = 0; l < 32; l += 2) {
            a0 += base[l * RSTRIDE_ + lane];
            a1 += base[(l + 1) * RSTRIDE_ + lane];
            b0 += base[l * RSTRIDE_ + lane + 27];
            b1 += base[(l + 1) * RSTRIDE_ + lane + 27];
        }
        tot0 = a0 + a1;
        tot1 = b0 + b1;
    }
    __syncwarp();
    if (lane < 27) {
        base[lane]      = tot0;
        base[lane + 27] = tot1;
    }
    __syncthreads();                         // totals + s_ss2 visible

    // ---- epilogue: lanes 0..4 handle shapelet s = lane ----
    if (lane < NS_) {
        const int s = lane;
        const float ss2v = s_ss2[s];
        float dmin = 3.402823466e+38f;
        float dsum = 0.f;
#pragma unroll
        for (int nb = 0; nb < NB_; nb++) {
            const float sx2t = base[nb];
            const float ct   = base[NB_ + s * NB_ + nb];
            const float d2 = sx2t + ss2v - 2.f * ct;
            const float d  = sqrtf(fmaxf(d2, 0.f));
            dmin = fminf(dmin, d);
            dsum += d;
        }
        float* fout = feat + (size_t)b * FEAT_;
        fout[s * V_ + v]            = dmin;
        fout[NS_ * V_ + s * V_ + v] = dsum * (1.f / 9.f);
    }
}

// ---------------------------------------------------------------------------
// Kernel 2 — merged tail, grid 90. Blocks 0..79: BN stats for feature f.
// Blocks 80..89: FC for class c (stage weights, spin on stats counter, go).
// All 90 blocks co-resident (<< 148 SMs) -> no deadlock. Counters self-reset.
// ---------------------------------------------------------------------------
__global__ __launch_bounds__(256, 8)
void tail_kernel(const float* __restrict__ feat,
                 const float* __restrict__ gamma,
                 const float* __restrict__ beta,
                 const float* __restrict__ w,
                 const float* __restrict__ fb,
                 float* __restrict__ scale,
                 float* __restrict__ shift,
                 float* __restrict__ out)
{
    const int tid = threadIdx.x;

    if (blockIdx.x < FEAT_) {
        // ---- BN stats for feature f (two-pass, wide) ----
        const int f = blockIdx.x;
        __shared__ float ws[8];
        __shared__ float wq[8];

        const float v = feat[tid * FEAT_ + f];

        float s = v;
#pragma unroll
        for (int o = 16; o > 0; o >>= 1) s += __shfl_xor_sync(0xffffffffu, s, o);
        if ((tid & 31) == 0) ws[tid >> 5] = s;
        __syncthreads();

        const float mu = (ws[0] + ws[1] + ws[2] + ws[3] +
                          ws[4] + ws[5] + ws[6] + ws[7]) * (1.f / 256.f);

        const float d = v - mu;
        float q = d * d;
#pragma unroll
        for (int o = 16; o > 0; o >>= 1) q += __shfl_xor_sync(0xffffffffu, q, o);
        if ((tid & 31) == 0) wq[tid >> 5] = q;
        __syncthreads();

        if (tid == 0) {
            const float var = (wq[0] + wq[1] + wq[2] + wq[3] +
                               wq[4] + wq[5] + wq[6] + wq[7]) * (1.f / 256.f);
            const float rstd = rsqrtf(var + BN_EPS_);
            const float sc = gamma[f] * rstd;
            scale[f] = sc;
            shift[f] = beta[f] - mu * sc;
            __threadfence();                 // release scale/shift
            atomicAdd(&g_done, 1);
        }
    } else {
        // ---- FC for class c ----
        const int c = blockIdx.x - FEAT_;
        __shared__ float wrow[FEAT_];
        __shared__ float wp[FEAT_];
        __shared__ float cbias;

        // stage weights while stats blocks run
        if (tid < FEAT_) wrow[tid] = w[c * FEAT_ + tid];

        if (tid == 0) {
            while (atomicAdd(&g_done, 0) < FEAT_) { }
            __threadfence();                 // acquire scale/shift
        }
        __syncthreads();

        if (tid < FEAT_) wp[tid] = wrow[tid] * scale[tid];

        if (tid >= 128 && tid < 160) {
            // warp 4 computes folded bias: fb[c] + sum_f shift[f]*w[c,f]
            const int lane = tid - 128;
            float a = 0.f;
            for (int f = lane; f < FEAT_; f += 32)
                a = fmaf(shift[f], wrow[f], a);
#pragma unroll
            for (int o = 16; o > 0; o >>= 1) a += __shfl_xor_sync(0xffffffffu, a, o);
            if (lane == 0) cbias = a + fb[c];
        }
        __syncthreads();

        const float4* __restrict__ fr = (const float4*)(feat + tid * FEAT_);
        float acc = cbias;
#pragma unroll
        for (int i = 0; i < FEAT_ / 4; i++) {
            float4 xv = fr[i];
            acc = fmaf(xv.x, wp[4 * i + 0], acc);
            acc = fmaf(xv.y, wp[4 * i + 1], acc);
            acc = fmaf(xv.z, wp[4 * i + 2], acc);
            acc = fmaf(xv.w, wp[4 * i + 3], acc);
        }
        out[tid * NCLASS_ + c] = acc;

        // counter self-reset: last FC block to finish clears both counters
        __syncthreads();
        if (tid == 0) {
            if (atomicAdd(&g_fc_done, 1) == NCLASS_ - 1) {
                g_fc_done = 0;
                g_done = 0;
            }
        }
    }
}

// ---------------------------------------------------------------------------
extern "C" void kernel_launch(void* const* d_in, const int* in_sizes, int n_in,
                              void* d_out, int out_size)
{
    const float* x     = (const float*)d_in[0];  // [256, 2048, 8]
    const float* shp   = (const float*)d_in[1];  // [1, 5, 8, 409, 1]
    const float* gamma = (const float*)d_in[2];  // [80]
    const float* beta  = (const float*)d_in[3];  // [80]
    const float* fcw   = (const float*)d_in[4];  // [10, 80]
    const float* fcb   = (const float*)d_in[5];  // [10]
    float* out = (float*)d_out;                  // [256, 10]

    float *feat = nullptr, *scale = nullptr, *shift = nullptr;
    cudaGetSymbolAddress((void**)&feat,  g_feat);
    cudaGetSymbolAddress((void**)&scale, g_scale);
    cudaGetSymbolAddress((void**)&shift, g_shift);

    static bool attr_set = false;
    if (!attr_set) {
        cudaFuncSetAttribute(shapelet_feat_kernel,
                             cudaFuncAttributeMaxDynamicSharedMemorySize,
                             (int)K1_DSMEM_);
        attr_set = true;
    }

    shapelet_feat_kernel<<<256, 256, K1_DSMEM_>>>(x, shp, feat);
    tail_kernel<<<FEAT_ + NCLASS_, 256>>>(feat, gamma, beta, fcw, fcb,
                                          scale, shift, out);
}